// round 1
// baseline (speedup 1.0000x reference)
#include <cuda_runtime.h>
#include <math.h>

// Problem constants
static constexpr int NB = 8;     // batch
static constexpr int NC = 256;   // channels
static constexpr int NH = 128;
static constexpr int NW = 128;
static constexpr int R  = 2;     // kernel radius (KS=5)
static constexpr float EPSF = 1e-8f;

// Tiling
static constexpr int TH = 16;
static constexpr int TW = 32;
static constexpr int HY = TH + 2;       // 18 rows (bottom halo only; half-shifts have dy>=0)
static constexpr int HX = TW + 4;       // 36 cols (left+right halo 2)
static constexpr int NPIX = HY * HX;    // 648
static constexpr int CC = 16;           // channels per chunk
static constexpr int NCHUNK = NC / CC;  // 16
static constexpr int NT = 512;          // threads per block
static constexpr int NSHIFT = 12;       // half of the 24 shifts (symmetry)

// Scratch (device globals; no allocation allowed)
__device__ float g_total[NB];
__device__ int   g_cnt[NB];
__device__ int   g_inc[NB];

__device__ __forceinline__ float dot4(float4 a, float4 b) {
    return a.x * b.x + a.y * b.y + a.z * b.z + a.w * b.w;
}

// ---------------------------------------------------------------------------
// Kernel 1: per-image valid-pixel count, include flag, zero totals.
// ---------------------------------------------------------------------------
__global__ void stats_kernel(const int* __restrict__ seg, const int* __restrict__ gtb) {
    int b = blockIdx.x;
    int tid = threadIdx.x;
    int cnt = 0, inc = 0;
    const int* segb = seg + b * NH * NW;
    const int* gtbb = gtb + b * NH * NW;
    for (int i = tid; i < NH * NW; i += blockDim.x) {
        int h = i / NW, w = i - (i / NW) * NW;
        int s = segb[i];
        int g = gtbb[i];
        int s0 = (s == 255) ? 0 : s;
        int g0 = (g == 255) ? 0 : g;
        if (s0 * g0 > 0) {
            inc = 1;
            if (h >= R && h < NH - R && w >= R && w < NW - R) cnt++;
        }
    }
    __shared__ int sc[256];
    __shared__ int si[256];
    sc[tid] = cnt; si[tid] = inc;
    __syncthreads();
    for (int s = 128; s > 0; s >>= 1) {
        if (tid < s) { sc[tid] += sc[tid + s]; si[tid] |= si[tid + s]; }
        __syncthreads();
    }
    if (tid == 0) {
        g_cnt[b]   = sc[0];
        g_inc[b]   = si[0];
        g_total[b] = 0.0f;
    }
}

// ---------------------------------------------------------------------------
// Kernel 2: main tiled dot-product accumulation.
// Each block: one 16x32 tile of one image. 512 threads, 1 core pixel each.
// Channel loop: stage 18x36 x 16-channel slab in SMEM (float4 layout),
// accumulate self-dot + 12 half-shift dots in registers.
// ---------------------------------------------------------------------------
__global__ __launch_bounds__(NT) void context_kernel(
    const float* __restrict__ er,
    const int* __restrict__ seg,
    const int* __restrict__ gtb)
{
    // SMEM: [CC/4][NPIX] float4 slab + norms + reduction scratch
    __shared__ float4 sh[(CC / 4) * NPIX];   // 4*648*16 = 41472 B
    __shared__ float  shNorm[NPIX];          // 2592 B
    __shared__ float  shRed[NT / 32];

    const int b  = blockIdx.z;
    const int h0 = blockIdx.y * TH;
    const int w0 = blockIdx.x * TW;
    const int tid = threadIdx.x;
    const int tx = tid & 31;
    const int ty = tid >> 5;
    const int mypix = ty * HX + (tx + 2);

    // half-shift offsets in halo-pixel coordinates (dy*HX + dx)
    const int doff[NSHIFT] = {1, 2,
                              HX - 2, HX - 1, HX, HX + 1, HX + 2,
                              2 * HX - 2, 2 * HX - 1, 2 * HX, 2 * HX + 1, 2 * HX + 2};

    const float* erb = er + (size_t)b * NC * NH * NW;

    float dots[NSHIFT];
#pragma unroll
    for (int d = 0; d < NSHIFT; d++) dots[d] = 0.0f;
    float selfA = 0.0f, selfB = 0.0f;   // distributed self-dots for all 648 halo pixels

    for (int cg = 0; cg < NCHUNK; cg++) {
        // --- stage slab: channels [cg*CC, cg*CC+CC), pixels = 18x36 halo region ---
        float* shf = (float*)sh;
        for (int i = tid; i < NPIX * CC; i += NT) {
            int cl  = i / NPIX;
            int pix = i - cl * NPIX;
            int ly  = pix / HX;
            int lx  = pix - ly * HX;
            int gh  = h0 + ly;
            int gw  = w0 - 2 + lx;
            float v = 0.0f;
            if (gh < NH && gw >= 0 && gw < NW)
                v = erb[((size_t)(cg * CC + cl) * NH + gh) * NW + gw];
            shf[(cl >> 2) * (NPIX * 4) + pix * 4 + (cl & 3)] = v;
        }
        __syncthreads();

        // --- accumulate dots ---
#pragma unroll
        for (int q = 0; q < CC / 4; q++) {
            const float4* row = sh + q * NPIX;
            float4 s = row[mypix];
#pragma unroll
            for (int d = 0; d < NSHIFT; d++) {
                float4 n = row[mypix + doff[d]];
                dots[d] += dot4(s, n);
            }
            // self-dots for norms, distributed over all 648 halo pixels
            float4 a = row[tid];
            selfA += dot4(a, a);
            if (tid + NT < NPIX) {
                float4 c = row[tid + NT];
                selfB += dot4(c, c);
            }
        }
        __syncthreads();
    }

    // --- norms to shared ---
    shNorm[tid] = fmaxf(sqrtf(selfA), EPSF);
    if (tid + NT < NPIX) shNorm[tid + NT] = fmaxf(sqrtf(selfB), EPSF);
    __syncthreads();

    // --- epilogue: per core pixel, combine 12 pair contributions ---
    const int gh = h0 + ty;
    const int gw = w0 + tx;
    const int* segb = seg + b * NH * NW;
    const int* gtbb = gtb + b * NH * NW;

    int sp = segb[gh * NW + gw];
    int gp = gtbb[gh * NW + gw];
    int s0p = (sp == 255) ? 0 : sp;
    int g0p = (gp == 255) ? 0 : gp;
    bool int_p = (gh >= R && gh < NH - R && gw >= R && gw < NW - R);
    float vp = (int_p && (s0p * g0p > 0)) ? 1.0f : 0.0f;
    float np = shNorm[mypix];

    const int dys[NSHIFT] = {0, 0, 1, 1, 1, 1, 1, 2, 2, 2, 2, 2};
    const int dxs[NSHIFT] = {1, 2, -2, -1, 0, 1, 2, -2, -1, 0, 1, 2};

    float acc = 0.0f;
#pragma unroll
    for (int d = 0; d < NSHIFT; d++) {
        int nh = gh + dys[d];
        int nw = gw + dxs[d];
        if (nh >= NH || nw < 0 || nw >= NW) continue;   // p would be non-interior too
        int sn = segb[nh * NW + nw];
        int gn = gtbb[nh * NW + nw];
        int s0n = (sn == 255) ? 0 : sn;
        int g0n = (gn == 255) ? 0 : gn;
        bool int_n = (nh >= R && nh < NH - R && nw >= R && nw < NW - R);
        float vn = (int_n && (s0n * g0n > 0)) ? 1.0f : 0.0f;
        float wgt = vp + vn;
        if (wgt == 0.0f) continue;
        float nn = shNorm[mypix + doff[d]];
        float cosv = dots[d] / (np * nn);
        float lab = (sp == sn && sp < 2) ? 1.0f : 0.0f;
        float diff = cosv - lab;
        acc += wgt * diff * diff;
    }

    // --- block reduce, atomic add per image ---
    unsigned mask = 0xFFFFFFFFu;
#pragma unroll
    for (int off = 16; off > 0; off >>= 1)
        acc += __shfl_down_sync(mask, acc, off);
    if ((tid & 31) == 0) shRed[tid >> 5] = acc;
    __syncthreads();
    if (tid < 32) {
        float r = (tid < NT / 32) ? shRed[tid] : 0.0f;
#pragma unroll
        for (int off = 8; off > 0; off >>= 1)
            r += __shfl_down_sync(mask, r, off);
        if (tid == 0) atomicAdd(&g_total[b], r);
    }
}

// ---------------------------------------------------------------------------
// Kernel 3: finalize scalar loss.
// ---------------------------------------------------------------------------
__global__ void final_kernel(float* __restrict__ out) {
    if (threadIdx.x == 0) {
        float sum = 0.0f;
        int sn = 0;
        for (int b = 0; b < NB; b++) {
            sn += g_inc[b];
            float cntf = fmaxf((float)g_cnt[b], 1.0f);
            float li = g_total[b] / cntf / 24.0f;
            if (g_inc[b]) sum += li;
        }
        int snn = (sn > 0) ? sn : 1;
        out[0] = sum / (float)snn;
    }
}

extern "C" void kernel_launch(void* const* d_in, const int* in_sizes, int n_in,
                              void* d_out, int out_size) {
    const float* er  = (const float*)d_in[0];
    const int*   seg = (const int*)d_in[1];
    const int*   gtb = (const int*)d_in[2];

    stats_kernel<<<NB, 256>>>(seg, gtb);
    dim3 grid(NW / TW, NH / TH, NB);   // 4 x 8 x 8 = 256 blocks
    context_kernel<<<grid, NT>>>(er, seg, gtb);
    final_kernel<<<1, 32>>>((float*)d_out);
}